// round 9
// baseline (speedup 1.0000x reference)
#include <cuda_runtime.h>
#include <math.h>

#define S_LEN  1024
#define B_SIZE 512
#define NTAG   48
#define PF     4
#define TMID   511
#define NCHUNK 64
#define CHUNK  (S_LEN / NCHUNK)

__device__ float g_fa[B_SIZE][64];
__device__ float g_bu[B_SIZE][64];
__device__ float g_Mf[B_SIZE];
__device__ float g_Mb[B_SIZE];
__device__ float g_pnum[NCHUNK][B_SIZE];
__device__ int   g_pcnt[NCHUNK][B_SIZE];

__device__ __forceinline__ unsigned long long pack2f(float lo, float hi) {
    unsigned long long r;
    asm("mov.b64 %0, {%1, %2};" : "=l"(r) : "f"(lo), "f"(hi));
    return r;
}
__device__ __forceinline__ void unpack2f(unsigned long long v, float& lo, float& hi) {
    asm("mov.b64 {%0, %1}, %2;" : "=f"(lo), "=f"(hi) : "l"(v));
}
__device__ __forceinline__ void ffma2(unsigned long long& acc,
                                      unsigned long long a, unsigned long long b) {
    asm("fma.rn.f32x2 %0, %1, %2, %0;" : "+l"(acc) : "l"(a), "l"(b));
}

// ---- one warp = one half-chain; blocks 0..511 fwd, 512..1023 bwd.
// Lane l owns tag pair (2l, 2l+1); lanes 24..31 are zero dummies.
// v-broadcast via warp shuffles of live registers: NO shared memory, NO syncs.
__global__ void __launch_bounds__(32)
crf_fwdbwd_kernel(const float* __restrict__ emissions,
                  const int* __restrict__ mask,
                  const float* __restrict__ start_t,
                  const float* __restrict__ end_t,
                  const float* __restrict__ trans)
{
    const int dir = blockIdx.x >> 9;
    const int b   = blockIdx.x & (B_SIZE - 1);
    const int l   = threadIdx.x;
    const int j0  = 2 * l;
    const int j1  = 2 * l + 1;
    const bool act = (l < NTAG / 2);      // l < 24

    // E2A[p] pairs i=(2p,2p+1) for output j0 ; E2B for output j1
    unsigned long long E2A[NTAG / 2], E2B[NTAG / 2];
    if (dir == 0) {
        // fwd: S[j] = sum_i v_i * exp(T[i][j])
#pragma unroll
        for (int p = 0; p < NTAG / 2; p++) {
            float a0 = act ? __expf(trans[(2 * p) * NTAG + j0]) : 0.f;
            float a1v = act ? __expf(trans[(2 * p + 1) * NTAG + j0]) : 0.f;
            float b0 = act ? __expf(trans[(2 * p) * NTAG + j1]) : 0.f;
            float b1 = act ? __expf(trans[(2 * p + 1) * NTAG + j1]) : 0.f;
            E2A[p] = pack2f(a0, a1v);
            E2B[p] = pack2f(b0, b1);
        }
    } else {
        // bwd: u[i] = sum_j exp(T[i][j]) * z_j   (rows of T)
#pragma unroll
        for (int p = 0; p < NTAG / 2; p++) {
            float a0 = act ? __expf(trans[j0 * NTAG + 2 * p]) : 0.f;
            float a1v = act ? __expf(trans[j0 * NTAG + 2 * p + 1]) : 0.f;
            float b0 = act ? __expf(trans[j1 * NTAG + 2 * p]) : 0.f;
            float b1 = act ? __expf(trans[j1 * NTAG + 2 * p + 1]) : 0.f;
            E2A[p] = pack2f(a0, a1v);
            E2B[p] = pack2f(b0, b1);
        }
    }

    float M = 0.f;
    int nupd = 0;
    float w0, w1;         // fwd: alpha pair; bwd: u pair
    float z0 = 0.f, z1 = 0.f;   // bwd only: z = u * exp(em)

    float2 pf[PF];

    if (dir == 0) {
        float2 em = act ? *(const float2*)(emissions + (size_t)b * NTAG + j0)
                        : make_float2(0.f, 0.f);
        w0 = act ? __expf(start_t[j0] + em.x) : 0.f;
        w1 = act ? __expf(start_t[act ? j1 : 0] + em.y) : 0.f;
#pragma unroll
        for (int k = 0; k < PF; k++) {
            int t = 1 + k;
            pf[t & (PF - 1)] = act ? *(const float2*)(emissions + ((size_t)t * B_SIZE + b) * NTAG + j0)
                                   : make_float2(0.f, 0.f);
        }
        unsigned mbits;
        {
            int mt = mask[(size_t)l * B_SIZE + b];
            mbits = __ballot_sync(0xffffffffu, mt != 0);
        }

#pragma unroll 4
        for (int t = 1; t <= TMID; t++) {
            if ((t & 31) == 0) {
                int mt = mask[(size_t)(t + l) * B_SIZE + b];
                mbits = __ballot_sync(0xffffffffu, mt != 0);
            }
            const int m_t = (mbits >> (t & 31)) & 1;

            const int slot = t & (PF - 1);
            const float e0 = __expf(pf[slot].x);
            const float e1 = __expf(pf[slot].y);
            int tn = t + PF; if (tn > TMID) tn = TMID;
            pf[slot] = act ? *(const float2*)(emissions + ((size_t)tn * B_SIZE + b) * NTAG + j0)
                           : make_float2(0.f, 0.f);

            unsigned long long accA0 = 0ull, accA1 = 0ull, accB0 = 0ull, accB1 = 0ull;
#pragma unroll
            for (int p = 0; p < NTAG / 2; p += 2) {
                unsigned long long vp0 = pack2f(__shfl_sync(0xffffffffu, w0, p),
                                                __shfl_sync(0xffffffffu, w1, p));
                unsigned long long vp1 = pack2f(__shfl_sync(0xffffffffu, w0, p + 1),
                                                __shfl_sync(0xffffffffu, w1, p + 1));
                ffma2(accA0, vp0, E2A[p]);
                ffma2(accB0, vp0, E2B[p]);
                ffma2(accA1, vp1, E2A[p + 1]);
                ffma2(accB1, vp1, E2B[p + 1]);
            }
            float a0, a1v, b0, b1, a2, a3, b2, b3;
            unpack2f(accA0, a0, a1v); unpack2f(accA1, a2, a3);
            unpack2f(accB0, b0, b1);  unpack2f(accB1, b2, b3);
            float nw0 = ((a0 + a1v) + (a2 + a3)) * e0;
            float nw1 = ((b0 + b1) + (b2 + b3)) * e1;

            if (m_t) {
                w0 = nw0; w1 = nw1;
                if (((++nupd) & 7) == 0) {
                    float r = fmaxf(w0, w1);
#pragma unroll
                    for (int o = 16; o > 0; o >>= 1)
                        r = fmaxf(r, __shfl_xor_sync(0xffffffffu, r, o));
                    r = fmaxf(r, 1e-30f);
                    M += __logf(r);
                    float inv = 1.f / r;
                    w0 *= inv; w1 *= inv;
                }
            }
        }
        g_fa[b][j0] = w0;
        g_fa[b][j1] = w1;
        if (l == 0) g_Mf[b] = M;
    } else {
        // ---- backward ----
        {
            float2 em = act ? *(const float2*)(emissions + ((size_t)(S_LEN - 1) * B_SIZE + b) * NTAG + j0)
                            : make_float2(0.f, 0.f);
            w0 = act ? __expf(end_t[j0]) : 0.f;
            w1 = act ? __expf(end_t[act ? j1 : 0]) : 0.f;
            z0 = w0 * __expf(em.x);
            z1 = w1 * __expf(em.y);
            if (!act) { z0 = 0.f; z1 = 0.f; }
        }
#pragma unroll
        for (int k = 0; k < PF; k++) {
            int t = 1022 - k;
            pf[t & (PF - 1)] = act ? *(const float2*)(emissions + ((size_t)t * B_SIZE + b) * NTAG + j0)
                                   : make_float2(0.f, 0.f);
        }
        unsigned mbits;
        {
            int mt = mask[(size_t)(992 + l) * B_SIZE + b];
            mbits = __ballot_sync(0xffffffffu, mt != 0);
        }

#pragma unroll 4
        for (int t = 1022; t >= TMID; t--) {
            const int tp1 = t + 1;
            if ((tp1 & 31) == 31) {
                int base = tp1 - 31;
                int mt = mask[(size_t)(base + l) * B_SIZE + b];
                mbits = __ballot_sync(0xffffffffu, mt != 0);
            }
            const int m_t = (mbits >> (tp1 & 31)) & 1;

            const int slot = t & (PF - 1);
            const float e0 = __expf(pf[slot].x);
            const float e1 = __expf(pf[slot].y);
            int tn = t - PF; if (tn < TMID) tn = TMID;
            pf[slot] = act ? *(const float2*)(emissions + ((size_t)tn * B_SIZE + b) * NTAG + j0)
                           : make_float2(0.f, 0.f);

            if (m_t) {   // uniform across warp
                unsigned long long accA0 = 0ull, accA1 = 0ull, accB0 = 0ull, accB1 = 0ull;
#pragma unroll
                for (int p = 0; p < NTAG / 2; p += 2) {
                    unsigned long long vp0 = pack2f(__shfl_sync(0xffffffffu, z0, p),
                                                    __shfl_sync(0xffffffffu, z1, p));
                    unsigned long long vp1 = pack2f(__shfl_sync(0xffffffffu, z0, p + 1),
                                                    __shfl_sync(0xffffffffu, z1, p + 1));
                    ffma2(accA0, vp0, E2A[p]);
                    ffma2(accB0, vp0, E2B[p]);
                    ffma2(accA1, vp1, E2A[p + 1]);
                    ffma2(accB1, vp1, E2B[p + 1]);
                }
                float a0, a1v, b0, b1, a2, a3, b2, b3;
                unpack2f(accA0, a0, a1v); unpack2f(accA1, a2, a3);
                unpack2f(accB0, b0, b1);  unpack2f(accB1, b2, b3);
                w0 = (a0 + a1v) + (a2 + a3);
                w1 = (b0 + b1) + (b2 + b3);
                if (((++nupd) & 7) == 0) {
                    float r = fmaxf(w0, w1);
#pragma unroll
                    for (int o = 16; o > 0; o >>= 1)
                        r = fmaxf(r, __shfl_xor_sync(0xffffffffu, r, o));
                    r = fmaxf(r, 1e-30f);
                    M += __logf(r);
                    float inv = 1.f / r;
                    w0 *= inv; w1 *= inv;
                }
            }
            if (t > TMID) {          // z for next iteration, from register copy
                z0 = w0 * e0;
                z1 = w1 * e1;
            }
        }
        g_bu[b][j0] = w0;
        g_bu[b][j1] = w1;
        if (l == 0) g_Mb[b] = M;
    }
}

// ---- numerator partials: coalesced over batch AND parallel (64 blocks) ----
__global__ void __launch_bounds__(B_SIZE)
crf_num_kernel(const float* __restrict__ emissions,
               const int* __restrict__ tags,
               const int* __restrict__ mask,
               const float* __restrict__ start_t,
               const float* __restrict__ trans)
{
    const int b  = threadIdx.x;
    const int c  = blockIdx.x;
    const int t0 = c * CHUNK;

    float acc = 0.f;
    int cnt = 0;
    int tp = (t0 > 0) ? tags[(t0 - 1) * B_SIZE + b] : 0;
#pragma unroll
    for (int k = 0; k < CHUNK; k++) {
        int t  = t0 + k;
        int tg = tags[t * B_SIZE + b];
        int m  = mask[t * B_SIZE + b];
        cnt += m;
        if (t == 0) {
            acc += start_t[tg] + emissions[(size_t)b * NTAG + tg];
        } else {
            acc += (trans[tp * NTAG + tg] +
                    emissions[((size_t)t * B_SIZE + b) * NTAG + tg]) * (float)m;
        }
        tp = tg;
    }
    g_pnum[c][b] = acc;
    g_pcnt[c][b] = cnt;
}

// ---- final: end-term + alpha.beta dot + mean ----
__global__ void __launch_bounds__(B_SIZE)
crf_reduce_kernel(float* __restrict__ out,
                  const int* __restrict__ tags,
                  const float* __restrict__ end_t)
{
    __shared__ float sh[B_SIZE];
    const int b = threadIdx.x;

    float num = 0.f;
    int cnt = 0;
#pragma unroll
    for (int c = 0; c < NCHUNK; c++) { num += g_pnum[c][b]; cnt += g_pcnt[c][b]; }
    num += end_t[tags[(cnt - 1) * B_SIZE + b]];

    float dot = 0.f;
    const float4* fa = (const float4*)g_fa[b];
    const float4* bu = (const float4*)g_bu[b];
#pragma unroll
    for (int k = 0; k < 16; k++) {
        float4 x = fa[k], y = bu[k];
        dot += x.x * y.x + x.y * y.y + x.z * y.z + x.w * y.w;
    }
    const float den = g_Mf[b] + g_Mb[b] + __logf(dot);

    sh[b] = num - den;
    __syncthreads();
#pragma unroll
    for (int o = B_SIZE / 2; o > 0; o >>= 1) {
        if (b < o) sh[b] += sh[b + o];
        __syncthreads();
    }
    if (b == 0) out[0] = sh[0] * (1.f / (float)B_SIZE);
}

extern "C" void kernel_launch(void* const* d_in, const int* in_sizes, int n_in,
                              void* d_out, int out_size)
{
    const float* emissions = (const float*)d_in[0];
    const int*   tags      = (const int*)d_in[1];
    const int*   mask      = (const int*)d_in[2];
    const float* start_t   = (const float*)d_in[3];
    const float* end_t     = (const float*)d_in[4];
    const float* trans     = (const float*)d_in[5];

    crf_fwdbwd_kernel<<<2 * B_SIZE, 32>>>(emissions, mask, start_t, end_t, trans);
    crf_num_kernel<<<NCHUNK, B_SIZE>>>(emissions, tags, mask, start_t, trans);
    crf_reduce_kernel<<<1, B_SIZE>>>((float*)d_out, tags, end_t);
}